// round 4
// baseline (speedup 1.0000x reference)
#include <cuda_runtime.h>
#include <math.h>

#define N_NODES 100000
#define N_EDGES 3200000
#define D_FEAT  128
#define HIDDEN  16
#define NCLS    8
#define NB_SCAN ((N_NODES + 255) / 256)   // 391

// ---- device scratch (allocation-free contract) ----
__device__ int    g_cnt[N_NODES];        // in-degree (dst)
__device__ int    g_excl[N_NODES];       // within-block exclusive scan
__device__ int    g_bsum[NB_SCAN];       // per-block sums
__device__ int    g_boff[NB_SCAN];       // exclusive block offsets
__device__ int    g_rowstart[N_NODES];   // CSR row starts (by dst)
__device__ int    g_fillpos[N_NODES];    // fill cursors
__device__ int    g_csrc[N_EDGES];       // CSR: src ids grouped by dst
__device__ float  g_dis[N_NODES];        // deg^-1/2 incl self-loop
__device__ float4 g_hn1[N_NODES * 4];    // (x@W1)*dis  [16 floats/node]
__device__ float4 g_a1 [N_NODES * 4];    // layer-1 aggregate
__device__ float4 g_hn2[N_NODES * 2];    // (h@W2)*dis  [8 floats/node]
__device__ float4 g_a2 [N_NODES * 2];    // layer-2 aggregate

// ---------------- prep ----------------
__global__ void k_zero_cnt() {
    int i = blockIdx.x * blockDim.x + threadIdx.x;
    if (i < N_NODES) g_cnt[i] = 0;
}

// count in-degree from the dst half of the int32 edge list
__global__ void k_count(const int* __restrict__ ei_dst) {
    int e = blockIdx.x * blockDim.x + threadIdx.x;
    if (e < N_EDGES) atomicAdd(&g_cnt[ei_dst[e]], 1);
}

// two-level exclusive scan of g_cnt -> g_rowstart
__global__ void k_scan1() {
    __shared__ int s[256];
    int tid = threadIdx.x;
    int i = blockIdx.x * 256 + tid;
    int v = (i < N_NODES) ? g_cnt[i] : 0;
    s[tid] = v;
    __syncthreads();
#pragma unroll
    for (int off = 1; off < 256; off <<= 1) {
        int t = (tid >= off) ? s[tid - off] : 0;
        __syncthreads();
        s[tid] += t;
        __syncthreads();
    }
    if (i < N_NODES) g_excl[i] = s[tid] - v;
    if (tid == 255) g_bsum[blockIdx.x] = s[255];
}

__global__ void k_scan2() {
    __shared__ int s[512];
    int tid = threadIdx.x;
    int v = (tid < NB_SCAN) ? g_bsum[tid] : 0;
    s[tid] = v;
    __syncthreads();
#pragma unroll
    for (int off = 1; off < 512; off <<= 1) {
        int t = (tid >= off) ? s[tid - off] : 0;
        __syncthreads();
        s[tid] += t;
        __syncthreads();
    }
    if (tid < NB_SCAN) g_boff[tid] = s[tid] - v;
}

__global__ void k_scan3() {
    int i = blockIdx.x * blockDim.x + threadIdx.x;
    if (i < N_NODES) {
        int rs = g_excl[i] + g_boff[i >> 8];
        g_rowstart[i] = rs;
        g_fillpos[i]  = rs;
        g_dis[i] = rsqrtf((float)(g_cnt[i] + 1));  // +1 self-loop
    }
}

// CSR fill: group src ids by dst (reads int32 edge list directly)
__global__ void k_fill(const int* __restrict__ ei) {
    int e = blockIdx.x * blockDim.x + threadIdx.x;
    if (e < N_EDGES) {
        int s = ei[e];
        int d = ei[N_EDGES + e];
        int pos = atomicAdd(&g_fillpos[d], 1);
        g_csrc[pos] = s;
    }
}

// ---------------- layer 1 GEMM: hn1 = (x @ W1) * dis ----------------
__global__ void k_gemm1(const float* __restrict__ x, const float* __restrict__ W1) {
    __shared__ float4 sW[D_FEAT * 4];  // 128 x 16 floats
    int tid = threadIdx.x;
    for (int t = tid; t < D_FEAT * 4; t += blockDim.x)
        sW[t] = ((const float4*)W1)[t];
    __syncthreads();

    int i = blockIdx.x * blockDim.x + tid;
    if (i >= N_NODES) return;

    float acc[HIDDEN];
#pragma unroll
    for (int j = 0; j < HIDDEN; j++) acc[j] = 0.0f;

    const float4* xr = (const float4*)(x + (size_t)i * D_FEAT);
#pragma unroll 4
    for (int k4 = 0; k4 < D_FEAT / 4; k4++) {
        float4 xv = xr[k4];
        float xk[4] = {xv.x, xv.y, xv.z, xv.w};
#pragma unroll
        for (int t = 0; t < 4; t++) {
            int k = k4 * 4 + t;
            float4 w0 = sW[k * 4 + 0];
            float4 w1 = sW[k * 4 + 1];
            float4 w2 = sW[k * 4 + 2];
            float4 w3 = sW[k * 4 + 3];
            acc[0]  = fmaf(xk[t], w0.x, acc[0]);
            acc[1]  = fmaf(xk[t], w0.y, acc[1]);
            acc[2]  = fmaf(xk[t], w0.z, acc[2]);
            acc[3]  = fmaf(xk[t], w0.w, acc[3]);
            acc[4]  = fmaf(xk[t], w1.x, acc[4]);
            acc[5]  = fmaf(xk[t], w1.y, acc[5]);
            acc[6]  = fmaf(xk[t], w1.z, acc[6]);
            acc[7]  = fmaf(xk[t], w1.w, acc[7]);
            acc[8]  = fmaf(xk[t], w2.x, acc[8]);
            acc[9]  = fmaf(xk[t], w2.y, acc[9]);
            acc[10] = fmaf(xk[t], w2.z, acc[10]);
            acc[11] = fmaf(xk[t], w2.w, acc[11]);
            acc[12] = fmaf(xk[t], w3.x, acc[12]);
            acc[13] = fmaf(xk[t], w3.y, acc[13]);
            acc[14] = fmaf(xk[t], w3.z, acc[14]);
            acc[15] = fmaf(xk[t], w3.w, acc[15]);
        }
    }

    float dis = g_dis[i];
#pragma unroll
    for (int q = 0; q < 4; q++)
        g_hn1[i * 4 + q] = make_float4(acc[q*4+0]*dis, acc[q*4+1]*dis,
                                       acc[q*4+2]*dis, acc[q*4+3]*dis);
}

// ------- layer 1 gather: a1[i] = hn1[i] + sum_{e: dst=i} hn1[src] -------
// 4 threads per node, one float4 chunk each; 64B/edge coalesced.
__global__ void k_gather1() {
    int idx = blockIdx.x * blockDim.x + threadIdx.x;
    int node = idx >> 2;
    int q = idx & 3;
    if (node >= N_NODES) return;
    int beg = g_rowstart[node];
    int end = beg + g_cnt[node];
    float4 acc = g_hn1[node * 4 + q];   // self-loop term
    for (int e = beg; e < end; e++) {
        int s = g_csrc[e];
        float4 v = g_hn1[s * 4 + q];
        acc.x += v.x; acc.y += v.y; acc.z += v.z; acc.w += v.w;
    }
    g_a1[node * 4 + q] = acc;
}

// ------- layer 2 prep: h = relu(dis*a1 + b1); hn2 = (h @ W2) * dis -------
__global__ void k_layer2(const float* __restrict__ W2, const float* __restrict__ b1) {
    __shared__ float4 sW2[HIDDEN * 2];
    __shared__ float  sb1[HIDDEN];
    int tid = threadIdx.x;
    if (tid < HIDDEN * 2) sW2[tid] = ((const float4*)W2)[tid];
    if (tid < HIDDEN)     sb1[tid] = b1[tid];
    __syncthreads();

    int i = blockIdx.x * blockDim.x + tid;
    if (i >= N_NODES) return;

    float dis = g_dis[i];
    float h[HIDDEN];
#pragma unroll
    for (int q = 0; q < 4; q++) {
        float4 v = g_a1[i * 4 + q];
        h[q*4+0] = fmaxf(fmaf(dis, v.x, sb1[q*4+0]), 0.0f);
        h[q*4+1] = fmaxf(fmaf(dis, v.y, sb1[q*4+1]), 0.0f);
        h[q*4+2] = fmaxf(fmaf(dis, v.z, sb1[q*4+2]), 0.0f);
        h[q*4+3] = fmaxf(fmaf(dis, v.w, sb1[q*4+3]), 0.0f);
    }

    float acc[NCLS];
#pragma unroll
    for (int c = 0; c < NCLS; c++) acc[c] = 0.0f;
#pragma unroll
    for (int k = 0; k < HIDDEN; k++) {
        float4 wA = sW2[k * 2 + 0];
        float4 wB = sW2[k * 2 + 1];
        acc[0] = fmaf(h[k], wA.x, acc[0]);
        acc[1] = fmaf(h[k], wA.y, acc[1]);
        acc[2] = fmaf(h[k], wA.z, acc[2]);
        acc[3] = fmaf(h[k], wA.w, acc[3]);
        acc[4] = fmaf(h[k], wB.x, acc[4]);
        acc[5] = fmaf(h[k], wB.y, acc[5]);
        acc[6] = fmaf(h[k], wB.z, acc[6]);
        acc[7] = fmaf(h[k], wB.w, acc[7]);
    }

    g_hn2[i * 2 + 0] = make_float4(acc[0]*dis, acc[1]*dis, acc[2]*dis, acc[3]*dis);
    g_hn2[i * 2 + 1] = make_float4(acc[4]*dis, acc[5]*dis, acc[6]*dis, acc[7]*dis);
}

// ------- layer 2 gather: a2[i] = hn2[i] + sum hn2[src]; 2 threads/node -------
__global__ void k_gather2() {
    int idx = blockIdx.x * blockDim.x + threadIdx.x;
    int node = idx >> 1;
    int q = idx & 1;
    if (node >= N_NODES) return;
    int beg = g_rowstart[node];
    int end = beg + g_cnt[node];
    float4 acc = g_hn2[node * 2 + q];   // self-loop term
    for (int e = beg; e < end; e++) {
        int s = g_csrc[e];
        float4 v = g_hn2[s * 2 + q];
        acc.x += v.x; acc.y += v.y; acc.z += v.z; acc.w += v.w;
    }
    g_a2[node * 2 + q] = acc;
}

// ------- final: logits = dis*a2 + b2; out = log_softmax(logits) -------
__global__ void k_final(const float* __restrict__ b2, float* __restrict__ out) {
    int i = blockIdx.x * blockDim.x + threadIdx.x;
    if (i >= N_NODES) return;
    float dis = g_dis[i];
    float4 u = g_a2[i * 2 + 0];
    float4 v = g_a2[i * 2 + 1];
    float l[NCLS];
    l[0] = fmaf(dis, u.x, __ldg(&b2[0]));
    l[1] = fmaf(dis, u.y, __ldg(&b2[1]));
    l[2] = fmaf(dis, u.z, __ldg(&b2[2]));
    l[3] = fmaf(dis, u.w, __ldg(&b2[3]));
    l[4] = fmaf(dis, v.x, __ldg(&b2[4]));
    l[5] = fmaf(dis, v.y, __ldg(&b2[5]));
    l[6] = fmaf(dis, v.z, __ldg(&b2[6]));
    l[7] = fmaf(dis, v.w, __ldg(&b2[7]));

    float m = l[0];
#pragma unroll
    for (int c = 1; c < NCLS; c++) m = fmaxf(m, l[c]);
    float s = 0.0f;
#pragma unroll
    for (int c = 0; c < NCLS; c++) s += expf(l[c] - m);
    float lse = m + logf(s);

    float4* op = (float4*)(out + (size_t)i * NCLS);
    op[0] = make_float4(l[0]-lse, l[1]-lse, l[2]-lse, l[3]-lse);
    op[1] = make_float4(l[4]-lse, l[5]-lse, l[6]-lse, l[7]-lse);
}

extern "C" void kernel_launch(void* const* d_in, const int* in_sizes, int n_in,
                              void* d_out, int out_size) {
    const float* x  = (const float*)d_in[0];
    const int*   ei = (const int*)d_in[1];     // int32! (JAX x64 disabled)
    const float* W1 = (const float*)d_in[2];
    const float* b1 = (const float*)d_in[3];
    const float* W2 = (const float*)d_in[4];
    const float* b2 = (const float*)d_in[5];
    float* out = (float*)d_out;

    const int NB_NODE = (N_NODES + 255) / 256;
    const int NB_EDGE = (N_EDGES + 255) / 256;
    const int NB_G1   = (N_NODES * 4 + 255) / 256;
    const int NB_G2   = (N_NODES * 2 + 255) / 256;

    k_zero_cnt <<<NB_NODE, 256>>>();
    k_count    <<<NB_EDGE, 256>>>(ei + N_EDGES);
    k_scan1    <<<NB_SCAN, 256>>>();
    k_scan2    <<<1,       512>>>();
    k_scan3    <<<NB_NODE, 256>>>();
    k_fill     <<<NB_EDGE, 256>>>(ei);
    k_gemm1    <<<(N_NODES + 127) / 128, 128>>>(x, W1);
    k_gather1  <<<NB_G1,   256>>>();
    k_layer2   <<<NB_NODE, 256>>>(W2, b1);
    k_gather2  <<<NB_G2,   256>>>();
    k_final    <<<NB_NODE, 256>>>(b2, out);
}